// round 15
// baseline (speedup 1.0000x reference)
#include <cuda_runtime.h>

#define T_    512
#define DF    64
#define NPAIR 60
#define NDIAG 1023
#define BIGV  1e10f
#define RS    1028
#define DTW_SMEM (15 * RS * 4)

static __device__ float g_Dd[(size_t)NPAIR * NDIAG * T_];   // anti-diagonal cost matrices
static __device__ float g_raw[NPAIR];
static __device__ float g_Gp[64 * 48 * 48];                 // gram partials per k-chunk

__device__ __forceinline__ float fex2(float x) { float y; asm("ex2.approx.f32 %0, %1;" : "=f"(y) : "f"(x)); return y; }
__device__ __forceinline__ float flg2(float x) { float y; asm("lg2.approx.f32 %0, %1;" : "=f"(y) : "f"(x)); return y; }

// packed f32x2 FMA (SASS FFMA2) + in-register duplication
__device__ __forceinline__ void ffma2(float2& d, float2 a, float2 b) {
    asm("fma.rn.f32x2 %0, %1, %2, %0;"
        : "+l"(*reinterpret_cast<unsigned long long*>(&d))
        : "l"(*reinterpret_cast<unsigned long long*>(&a)),
          "l"(*reinterpret_cast<unsigned long long*>(&b)));
}
__device__ __forceinline__ float2 dup2(float a) {
    float2 r;
    asm("mov.b64 %0, {%1, %1};"
        : "=l"(*reinterpret_cast<unsigned long long*>(&r)) : "f"(a));
    return r;
}

// ---------------------------------------------------------------------------
// Kernel A: squared-Euclidean cost tiles -> anti-diagonal layout g_Dd[p][i+j][i]
// (FFMA2 + in-register dup: measured 56.4us) — unchanged from R13
// ---------------------------------------------------------------------------
__global__ __launch_bounds__(256) void cost_kernel(const float* __restrict__ data,
                                                   const int* __restrict__ lens) {
    int p = blockIdx.z;
    int w = p / 15, jj = p % 15 + 1;
    int arow = w * 16, brow = arow + jj;
    int la = lens[arow], lb = lens[brow];
    int i0 = blockIdx.y * 64, j0 = blockIdx.x * 64;
    if (i0 >= la || j0 >= lb) return;

    __shared__ float As[64][68];
    __shared__ float Bs[64][68];
    __shared__ float Ct[64][66];
    __shared__ float a2s[64], b2s[64];

    int tid = threadIdx.x;
    const float* Ap = data + (size_t)arow * T_ * DF;
    const float* Bp = data + (size_t)brow * T_ * DF;
#pragma unroll
    for (int it = 0; it < 4; ++it) {
        int f = tid + it * 256;
        int r = f >> 4, q = f & 15;
        float4 va = *(const float4*)(Ap + (size_t)(i0 + r) * DF + q * 4);
        float4 vb = *(const float4*)(Bp + (size_t)(j0 + r) * DF + q * 4);
        As[q * 4 + 0][r] = va.x; As[q * 4 + 1][r] = va.y; As[q * 4 + 2][r] = va.z; As[q * 4 + 3][r] = va.w;
        Bs[q * 4 + 0][r] = vb.x; Bs[q * 4 + 1][r] = vb.y; Bs[q * 4 + 2][r] = vb.z; Bs[q * 4 + 3][r] = vb.w;
    }
    __syncthreads();

    if (tid < 64) {
        float s = 0.f;
#pragma unroll
        for (int k = 0; k < 64; ++k) { float v = As[k][tid]; s = fmaf(v, v, s); }
        a2s[tid] = s;
    } else if (tid < 128) {
        int r = tid - 64; float s = 0.f;
#pragma unroll
        for (int k = 0; k < 64; ++k) { float v = Bs[k][r]; s = fmaf(v, v, s); }
        b2s[r] = s;
    }

    int tx = tid & 15, ty = tid >> 4;
    int ib = ty * 4, jb = tx * 4;
    float2 acc2[4][2] = {};
#pragma unroll 16
    for (int k = 0; k < 64; ++k) {
        float4 av = *(const float4*)&As[k][ib];
        float4 bv = *(const float4*)&Bs[k][jb];
        float2 b01 = make_float2(bv.x, bv.y), b23 = make_float2(bv.z, bv.w);
        float2 a0 = dup2(av.x), a1 = dup2(av.y), a2 = dup2(av.z), a3 = dup2(av.w);
        ffma2(acc2[0][0], a0, b01); ffma2(acc2[0][1], a0, b23);
        ffma2(acc2[1][0], a1, b01); ffma2(acc2[1][1], a1, b23);
        ffma2(acc2[2][0], a2, b01); ffma2(acc2[2][1], a2, b23);
        ffma2(acc2[3][0], a3, b01); ffma2(acc2[3][1], a3, b23);
    }
    __syncthreads();
#pragma unroll
    for (int r = 0; r < 4; ++r) {
        float a2v = a2s[ib + r];
        Ct[ib + r][jb + 0] = a2v + b2s[jb + 0] - 2.f * acc2[r][0].x;
        Ct[ib + r][jb + 1] = a2v + b2s[jb + 1] - 2.f * acc2[r][0].y;
        Ct[ib + r][jb + 2] = a2v + b2s[jb + 2] - 2.f * acc2[r][1].x;
        Ct[ib + r][jb + 3] = a2v + b2s[jb + 3] - 2.f * acc2[r][1].y;
    }
    __syncthreads();

    float* Dp = g_Dd + (size_t)p * NDIAG * T_;
    int kdo = tid >> 6, t = tid & 63;
    for (int kd0 = 0; kd0 < 127; kd0 += 4) {
        int kd = kd0 + kdo;
        if (kd < 127) {
            int ilo = kd > 63 ? kd - 63 : 0;
            int ihi = kd < 63 ? kd : 63;
            int ci = ilo + t;
            if (ci <= ihi) {
                int cj = kd - ci;
                Dp[(size_t)(i0 + ci + j0 + cj) * T_ + (i0 + ci)] = Ct[ci][cj];
            }
        }
    }
}

// ---------------------------------------------------------------------------
// gram body (blocks 60..123 of the fused kernel, 512 threads) — unchanged
// ---------------------------------------------------------------------------
__device__ void gram_body(const float* __restrict__ data, int bid, int tid) {
    __shared__ float St[64][49];
    int tx = tid & 15, ty = (tid >> 4) & 15;
    float acc[3][3] = {};
    int k0 = bid * 512;
    for (int sub = 0; sub < 8; ++sub) {
        int kb = k0 + sub * 64;
        __syncthreads();
        for (int f = tid; f < 44 * 16; f += 512) {
            int r = f >> 4, q = f & 15;
            int n = (r / 11) * 16 + (r % 11);
            float4 v = *(const float4*)(data + (size_t)n * 32768 + kb + q * 4);
            St[q * 4 + 0][r] = v.x; St[q * 4 + 1][r] = v.y;
            St[q * 4 + 2][r] = v.z; St[q * 4 + 3][r] = v.w;
        }
        if (tid < 256) { int kk = tid >> 2; int r = 44 + (tid & 3); St[kk][r] = 0.f; }
        __syncthreads();
        if (tid < 256) {
#pragma unroll 8
            for (int kk = 0; kk < 64; ++kk) {
                float a0 = St[kk][ty * 3 + 0], a1 = St[kk][ty * 3 + 1], a2 = St[kk][ty * 3 + 2];
                float b0 = St[kk][tx * 3 + 0], b1 = St[kk][tx * 3 + 1], b2 = St[kk][tx * 3 + 2];
                acc[0][0] = fmaf(a0, b0, acc[0][0]); acc[0][1] = fmaf(a0, b1, acc[0][1]); acc[0][2] = fmaf(a0, b2, acc[0][2]);
                acc[1][0] = fmaf(a1, b0, acc[1][0]); acc[1][1] = fmaf(a1, b1, acc[1][1]); acc[1][2] = fmaf(a1, b2, acc[1][2]);
                acc[2][0] = fmaf(a2, b0, acc[2][0]); acc[2][1] = fmaf(a2, b1, acc[2][1]); acc[2][2] = fmaf(a2, b2, acc[2][2]);
            }
        }
    }
    if (tid < 256) {
        float* gp = g_Gp + bid * 2304;
#pragma unroll
        for (int r = 0; r < 3; ++r)
#pragma unroll
            for (int c = 0; c < 3; ++c)
                gp[(ty * 3 + r) * 48 + (tx * 3 + c)] = acc[r][c];
    }
}

// ---------------------------------------------------------------------------
// Kernel B (fused, 512 threads): blocks [0,60): soft-DTW, async window
// pipeline — NO block barriers in the main loop. Each warp processes only its
// own windows t = w..thi. Producer lane 31 publishes a monotonic counter
// (st.release) after each window; consumer lane 0 acquire-spins once per
// window (counting semantics — fixes R14's named-barrier credit loss).
// bnd is full-length (no ring) in dynamic smem. Blocks [60,124): gram.
// ---------------------------------------------------------------------------
extern __shared__ float dyn_bnd[];   // [15][RS]: bnd[w*RS + k] = R(k, row 32w+32)

__global__ __launch_bounds__(512) void dtw_gram_kernel(const float* __restrict__ data,
                                                       const int* __restrict__ lens) {
    int bid = blockIdx.x;
    int tid = threadIdx.x;
    if (bid >= NPAIR) { gram_body(data, bid - NPAIR, tid); return; }

    __shared__ int cnts[15];
    float* bnd = dyn_bnd;
    for (int q = tid; q < 15 * RS; q += 512) bnd[q] = BIGV;
    if (tid < 15) cnts[tid] = 0;
    __syncthreads();

    int w = bid / 15, jj = bid % 15 + 1;
    int la = lens[w * 16], lb = lens[w * 16 + jj];
    int kmax = la + lb;
    int warp = tid >> 5, lane = tid & 31;
    int i = tid + 1;                              // this thread's DP row

    const float* Dp = g_Dd + (size_t)bid * NDIAG * T_;
    const float c1 = 0.28853900817779268f;       // 1/(GAMMA*ln2)
    const float gln2 = 3.4657359027997265f;      // GAMMA*ln2

    float p1 = BIGV;                              // R(k-1, i)
    float n1p = (tid == 0) ? 0.f : BIGV;          // previous n1 -> R(k-2, i-1)

    int nblk = (kmax - 1 + 31) >> 5;              // windows covering diag 2..kmax
    bool rowact = (32 * warp + 1) <= la;
    int thi = min(nblk - 1, (32 * warp + 30 + lb) >> 5);
    int thi_prev = (warp > 0) ? min(nblk - 1, (32 * (warp - 1) + 30 + lb) >> 5) : 0;

    unsigned cntPrev = (warp > 0) ? (unsigned)__cvta_generic_to_shared(&cnts[warp - 1]) : 0u;
    unsigned cntOwn  = (warp < 15) ? (unsigned)__cvta_generic_to_shared(&cnts[warp]) : 0u;
    const float* bndPrev = bnd + (warp - 1) * RS;
    float* bndOwn = bnd + warp * RS;
    int seen = 0;

    if (rowact) {
        for (int t = warp; t <= thi; ++t) {
            int k0 = 2 + t * 32;
            float cs[32];                          // issue loads BEFORE the wait
#pragma unroll
            for (int d = 0; d < 32; ++d)
                cs[d] = Dp[(size_t)min(k0 - 2 + d, NDIAG - 1) * T_ + tid];

            if (warp > 0 && lane == 0) {           // wait: producer window min(t,thi_prev) done
                int need = 32 * min(t, thi_prev) + 33;
                while (seen < need)
                    asm volatile("ld.acquire.cta.shared.b32 %0, [%1];"
                                 : "=r"(seen) : "r"(cntPrev) : "memory");
            }

            bool full = (32 * warp + 32 <= la) && (k0 >= 32 * warp + 33)
                     && (k0 + 31 <= 32 * warp + 1 + lb);
            if (full) {
#pragma unroll
                for (int d = 0; d < 32; ++d) {
                    int k = k0 + d;
                    float n1 = __shfl_up_sync(0xffffffffu, p1, 1);
                    if (lane == 0)
                        n1 = (warp == 0) ? BIGV : bndPrev[k - 1];
                    float pmn = fminf(n1, n1p);
                    float pmx = fmaxf(n1, n1p);
                    float psm = n1 + n1p;
                    n1p = n1;
                    float m = fminf(pmn, p1);
                    float M = fmaxf(pmx, p1);
                    float mid = (psm + p1) - m - M;
                    float S2 = 1.f + fex2((m - mid) * c1) + fex2((m - M) * c1);
                    float r = cs[d] + m - gln2 * flg2(S2);
                    p1 = r;
                    if (lane == 31 && warp < 15) bndOwn[k] = r;
                }
            } else {
                bool iact = (i <= la);
#pragma unroll
                for (int d = 0; d < 32; ++d) {
                    int k = k0 + d;
                    float n1 = __shfl_up_sync(0xffffffffu, p1, 1);
                    if (lane == 0)
                        n1 = (warp == 0) ? BIGV : bndPrev[k - 1];
                    float pmn = fminf(n1, n1p);
                    float pmx = fmaxf(n1, n1p);
                    float psm = n1 + n1p;
                    n1p = n1;
                    float m = fminf(pmn, p1);
                    float M = fmaxf(pmx, p1);
                    float mid = (psm + p1) - m - M;
                    float S2 = 1.f + fex2((m - mid) * c1) + fex2((m - M) * c1);
                    float r = cs[d] + m - gln2 * flg2(S2);
                    bool act = iact && (k > i) && (k <= i + lb);
                    r = act ? r : BIGV;
                    p1 = r;
                    if (lane == 31 && warp < 15) bndOwn[k] = r;
                    if (k == kmax && i == la) g_raw[bid] = r;
                }
            }
            if (lane == 31 && warp < 15)           // publish window completion
                asm volatile("st.release.cta.shared.b32 [%0], %1;"
                             :: "r"(cntOwn), "r"(32 * t + 33) : "memory");
        }
    }
}

// ---------------------------------------------------------------------------
// Kernel C: finishing — parallel reductions (deterministic fixed-order trees)
// ---------------------------------------------------------------------------
__device__ __forceinline__ float warp_sum(float v) {
#pragma unroll
    for (int o = 16; o; o >>= 1) v += __shfl_down_sync(0xffffffffu, v, o);
    return v;
}

__device__ float block_sum(float v, float* part, int tid) {
    float s = warp_sum(v);
    __syncthreads();
    if ((tid & 31) == 0) part[tid >> 5] = s;
    __syncthreads();
    if (tid < 32) {
        float x = (tid < 16) ? part[tid] : 0.f;
        x = warp_sum(x);
        if (tid == 0) part[0] = x;
    }
    __syncthreads();
    return part[0];
}

__global__ __launch_bounds__(512) void final_kernel(const int* __restrict__ lens,
                                                    float* __restrict__ out) {
    __shared__ float sG[44 * 44];
    __shared__ float part[32];
    __shared__ float dist[60];
    __shared__ float sTotal;
    int tid = threadIdx.x;

    for (int t = tid; t < 44 * 44; t += 512) {
        int a = t / 44, b = t % 44;
        float s = 0.f;
#pragma unroll 8
        for (int blk = 0; blk < 64; ++blk) s += g_Gp[blk * 2304 + a * 48 + b];
        sG[t] = s;
    }
    if (tid < 60) {
        int w = tid / 15, jj = tid % 15 + 1;
        dist[tid] = g_raw[tid] / (float)(lens[w * 16] + lens[w * 16 + jj]);
    }
    __syncthreads();

    if (tid == 0) {
        float total = 0.f;
        for (int w = 0; w < 4; ++w) {
            const float* dw = dist + w * 15;
            float mg = 0.f;
            for (int g = 0; g < 5; ++g) mg += dw[g];
            mg *= 0.2f;
            float dk = sqrtf(fabsf(mg));
            float dg[5], dn[10];
            for (int g = 0; g < 5; ++g) dg[g] = dw[g] / dk;
            for (int s = 0; s < 10; ++s) dn[s] = dw[5 + s] / dk;
            float sum = 0.f; int cnt = 0;
            for (int g = 0; g < 5; ++g)
                for (int s = 0; s < 10; ++s) {
                    float v = dg[g] + 1.0f - dn[s];
                    if (v > 0.f) { sum += v; cnt++; }
                }
            float ca = 0.f, cb = 0.f;
            for (int g = 0; g < 5; ++g) ca += dg[g];
            ca *= 0.2f;
            for (int s = 0; s < 5; ++s) cb += dn[s];
            cb *= 0.2f;
            float intra = 0.f;
            for (int g = 0; g < 5; ++g) intra += dg[g] - ca;
            float inter = fmaxf(0.f, 1.0f - fabsf(ca - cb));
            float lv = sum / ((float)cnt + 1.f);
            total += lv + intra * 0.1f + inter * 0.1f;
        }
        sTotal = total * 0.25f;
    }
    __syncthreads();

    const int pwi[9] = {0, 0, 0, 1, 1, 2, 2, 3, 3};
    const int pwj[9] = {1, 2, 3, 2, 3, 1, 3, 1, 2};
    int a = tid / 22, b = tid % 22;
    float mmax = 0.f;
#pragma unroll 1
    for (int pp = 0; pp < 9; ++pp) {
        float l2 = 0.f;
        if (tid < 484) {
            int ra = (a < 11) ? pwi[pp] * 11 + a : pwj[pp] * 11 + (a - 11);
            int rb = (b < 11) ? pwi[pp] * 11 + b : pwj[pp] * 11 + (b - 11);
            l2 = sG[ra * 44 + ra] + sG[rb * 44 + rb] - 2.f * sG[ra * 44 + rb];
        }
        float bw = block_sum(l2, part, tid) * (0.25f / 462.f);
        float kk = 0.f;
        if (tid < 484) {
            float r0 = -l2 / bw * 1.4426950408889634f;   // log2(e)
            kk = fex2(r0) + fex2(r0 * 0.5f) + fex2(r0 * 0.25f)
               + fex2(r0 * 0.125f) + fex2(r0 * 0.0625f);
        }
        float sgn = ((a < 11) == (b < 11)) ? kk : -kk;
        float msum = block_sum(tid < 484 ? sgn : 0.f, part, tid);
        mmax = fmaxf(mmax, msum * (1.f / 121.f));
    }
    if (tid == 0) out[0] = sTotal + mmax * 0.1f;
}

// ---------------------------------------------------------------------------
extern "C" void kernel_launch(void* const* d_in, const int* in_sizes, int n_in,
                              void* d_out, int out_size) {
    const float* data = (const float*)d_in[0];
    const int* lens = (const int*)d_in[1];
    float* out = (float*)d_out;

    cudaFuncSetAttribute(dtw_gram_kernel,
                         cudaFuncAttributeMaxDynamicSharedMemorySize, DTW_SMEM);

    dim3 gA(8, 8, NPAIR);
    cost_kernel<<<gA, 256>>>(data, lens);
    dtw_gram_kernel<<<NPAIR + 64, 512, DTW_SMEM>>>(data, lens);
    final_kernel<<<1, 512>>>(lens, out);
}

// round 16
// speedup vs baseline: 1.9339x; 1.9339x over previous
#include <cuda_runtime.h>

#define T_    512
#define DF    64
#define NPAIR 60
#define NDIAG 1023
#define BIGV  1e10f
#define RSG   1056

static __device__ float g_Dd[(size_t)NPAIR * NDIAG * T_];   // anti-diagonal cost matrices
static __device__ float g_raw[NPAIR];
static __device__ float g_Gp[64 * 48 * 48];                 // gram partials per k-chunk
static __device__ float g_bnd[NPAIR * RSG];                 // row-256 boundary per pair
static __device__ int   g_cnt[NPAIR];                       // monotone publish counter

__device__ __forceinline__ float fex2(float x) { float y; asm("ex2.approx.f32 %0, %1;" : "=f"(y) : "f"(x)); return y; }
__device__ __forceinline__ float flg2(float x) { float y; asm("lg2.approx.f32 %0, %1;" : "=f"(y) : "f"(x)); return y; }

__device__ __forceinline__ void ffma2(float2& d, float2 a, float2 b) {
    asm("fma.rn.f32x2 %0, %1, %2, %0;"
        : "+l"(*reinterpret_cast<unsigned long long*>(&d))
        : "l"(*reinterpret_cast<unsigned long long*>(&a)),
          "l"(*reinterpret_cast<unsigned long long*>(&b)));
}
__device__ __forceinline__ float2 dup2(float a) {
    float2 r;
    asm("mov.b64 %0, {%1, %1};"
        : "=l"(*reinterpret_cast<unsigned long long*>(&r)) : "f"(a));
    return r;
}

// ---------------------------------------------------------------------------
// Kernel A: cost tiles -> anti-diagonal layout (FFMA2+dup2, measured 56.4us)
// + zero g_cnt each replay (block (0,0,0) runs before the dtw kernel launch)
// ---------------------------------------------------------------------------
__global__ __launch_bounds__(256) void cost_kernel(const float* __restrict__ data,
                                                   const int* __restrict__ lens) {
    if (blockIdx.x == 0 && blockIdx.y == 0 && blockIdx.z == 0 && threadIdx.x < NPAIR)
        g_cnt[threadIdx.x] = 0;

    int p = blockIdx.z;
    int w = p / 15, jj = p % 15 + 1;
    int arow = w * 16, brow = arow + jj;
    int la = lens[arow], lb = lens[brow];
    int i0 = blockIdx.y * 64, j0 = blockIdx.x * 64;
    if (i0 >= la || j0 >= lb) return;

    __shared__ float As[64][68];
    __shared__ float Bs[64][68];
    __shared__ float Ct[64][66];
    __shared__ float a2s[64], b2s[64];

    int tid = threadIdx.x;
    const float* Ap = data + (size_t)arow * T_ * DF;
    const float* Bp = data + (size_t)brow * T_ * DF;
#pragma unroll
    for (int it = 0; it < 4; ++it) {
        int f = tid + it * 256;
        int r = f >> 4, q = f & 15;
        float4 va = *(const float4*)(Ap + (size_t)(i0 + r) * DF + q * 4);
        float4 vb = *(const float4*)(Bp + (size_t)(j0 + r) * DF + q * 4);
        As[q * 4 + 0][r] = va.x; As[q * 4 + 1][r] = va.y; As[q * 4 + 2][r] = va.z; As[q * 4 + 3][r] = va.w;
        Bs[q * 4 + 0][r] = vb.x; Bs[q * 4 + 1][r] = vb.y; Bs[q * 4 + 2][r] = vb.z; Bs[q * 4 + 3][r] = vb.w;
    }
    __syncthreads();

    if (tid < 64) {
        float s = 0.f;
#pragma unroll
        for (int k = 0; k < 64; ++k) { float v = As[k][tid]; s = fmaf(v, v, s); }
        a2s[tid] = s;
    } else if (tid < 128) {
        int r = tid - 64; float s = 0.f;
#pragma unroll
        for (int k = 0; k < 64; ++k) { float v = Bs[k][r]; s = fmaf(v, v, s); }
        b2s[r] = s;
    }

    int tx = tid & 15, ty = tid >> 4;
    int ib = ty * 4, jb = tx * 4;
    float2 acc2[4][2] = {};
#pragma unroll 16
    for (int k = 0; k < 64; ++k) {
        float4 av = *(const float4*)&As[k][ib];
        float4 bv = *(const float4*)&Bs[k][jb];
        float2 b01 = make_float2(bv.x, bv.y), b23 = make_float2(bv.z, bv.w);
        float2 a0 = dup2(av.x), a1 = dup2(av.y), a2 = dup2(av.z), a3 = dup2(av.w);
        ffma2(acc2[0][0], a0, b01); ffma2(acc2[0][1], a0, b23);
        ffma2(acc2[1][0], a1, b01); ffma2(acc2[1][1], a1, b23);
        ffma2(acc2[2][0], a2, b01); ffma2(acc2[2][1], a2, b23);
        ffma2(acc2[3][0], a3, b01); ffma2(acc2[3][1], a3, b23);
    }
    __syncthreads();
#pragma unroll
    for (int r = 0; r < 4; ++r) {
        float a2v = a2s[ib + r];
        Ct[ib + r][jb + 0] = a2v + b2s[jb + 0] - 2.f * acc2[r][0].x;
        Ct[ib + r][jb + 1] = a2v + b2s[jb + 1] - 2.f * acc2[r][0].y;
        Ct[ib + r][jb + 2] = a2v + b2s[jb + 2] - 2.f * acc2[r][1].x;
        Ct[ib + r][jb + 3] = a2v + b2s[jb + 3] - 2.f * acc2[r][1].y;
    }
    __syncthreads();

    float* Dp = g_Dd + (size_t)p * NDIAG * T_;
    int kdo = tid >> 6, t = tid & 63;
    for (int kd0 = 0; kd0 < 127; kd0 += 4) {
        int kd = kd0 + kdo;
        if (kd < 127) {
            int ilo = kd > 63 ? kd - 63 : 0;
            int ihi = kd < 63 ? kd : 63;
            int ci = ilo + t;
            if (ci <= ihi) {
                int cj = kd - ci;
                Dp[(size_t)(i0 + ci + j0 + cj) * T_ + (i0 + ci)] = Ct[ci][cj];
            }
        }
    }
}

// ---------------------------------------------------------------------------
// gram body (blocks 120..183, 256 threads)
// ---------------------------------------------------------------------------
__device__ void gram_body(const float* __restrict__ data, int bid, int tid) {
    __shared__ float St[64][49];
    int tx = tid & 15, ty = (tid >> 4) & 15;
    float acc[3][3] = {};
    int k0 = bid * 512;
    for (int sub = 0; sub < 8; ++sub) {
        int kb = k0 + sub * 64;
        __syncthreads();
        for (int f = tid; f < 44 * 16; f += 256) {
            int r = f >> 4, q = f & 15;
            int n = (r / 11) * 16 + (r % 11);
            float4 v = *(const float4*)(data + (size_t)n * 32768 + kb + q * 4);
            St[q * 4 + 0][r] = v.x; St[q * 4 + 1][r] = v.y;
            St[q * 4 + 2][r] = v.z; St[q * 4 + 3][r] = v.w;
        }
        { int kk = tid >> 2; int r = 44 + (tid & 3); St[kk][r] = 0.f; }
        __syncthreads();
#pragma unroll 8
        for (int kk = 0; kk < 64; ++kk) {
            float a0 = St[kk][ty * 3 + 0], a1 = St[kk][ty * 3 + 1], a2 = St[kk][ty * 3 + 2];
            float b0 = St[kk][tx * 3 + 0], b1 = St[kk][tx * 3 + 1], b2 = St[kk][tx * 3 + 2];
            acc[0][0] = fmaf(a0, b0, acc[0][0]); acc[0][1] = fmaf(a0, b1, acc[0][1]); acc[0][2] = fmaf(a0, b2, acc[0][2]);
            acc[1][0] = fmaf(a1, b0, acc[1][0]); acc[1][1] = fmaf(a1, b1, acc[1][1]); acc[1][2] = fmaf(a1, b2, acc[1][2]);
            acc[2][0] = fmaf(a2, b0, acc[2][0]); acc[2][1] = fmaf(a2, b1, acc[2][1]); acc[2][2] = fmaf(a2, b2, acc[2][2]);
        }
    }
    float* gp = g_Gp + bid * 2304;
#pragma unroll
    for (int r = 0; r < 3; ++r)
#pragma unroll
        for (int c = 0; c < 3; ++c)
            gp[(ty * 3 + r) * 48 + (tx * 3 + c)] = acc[r][c];
}

// ---------------------------------------------------------------------------
// Kernel B (fused, 256 threads): blocks [0,120): soft-DTW, each PAIR split
// across 2 CTAs (half 0: rows 1-256 / global warps 0-7; half 1: rows 257-512
// / global warps 8-15). Inside each CTA: R13's exact convoy (W=32 windows,
// __syncthreads per phase, in-chain lane-0 LDS). The row-256 boundary crosses
// CTAs via gmem: producer warp 7 lane 31 stores g_bnd per step + one
// st.release.gpu counter per window; consumer warp 0 waits once per window
// (all lanes poll one address), stages 32 values into local smem row bnd[7],
// then runs the identical chain. Monotone counter + full co-residency
// (184 CTAs x 256thr <= capacity) => deadlock-free. Blocks [120,184): gram.
// ---------------------------------------------------------------------------
__global__ __launch_bounds__(256) void dtw_gram_kernel(const float* __restrict__ data,
                                                       const int* __restrict__ lens) {
    int bid = blockIdx.x;
    int tid = threadIdx.x;
    if (bid >= 2 * NPAIR) { gram_body(data, bid - 2 * NPAIR, tid); return; }

    __shared__ float bnd[8][128];   // [0..6]: local warp boundaries; [7]: staged incoming

    int pair = bid >> 1, half = bid & 1;
    int w = pair / 15, jj = pair % 15 + 1;
    int la = lens[w * 16], lb = lens[w * 16 + jj];
    int kmax = la + lb;
    int warp = tid >> 5, lane = tid & 31;
    int g = half * 8 + warp;                      // global warp id 0..15
    int i = half * 256 + tid + 1;                 // this thread's DP row

    const float* Dp = g_Dd + (size_t)pair * NDIAG * T_;
    const float c1 = 0.28853900817779268f;       // 1/(GAMMA*ln2)
    const float gln2 = 3.4657359027997265f;      // GAMMA*ln2

    float p1 = BIGV;                              // R(k-1, i)
    float n1p = (half == 0 && tid == 0) ? 0.f : BIGV;   // R(k-2, i-1); row1 seed R(0,0)=0

    int nblk = (kmax - 1 + 31) >> 5;
    int nph = nblk + 7;                           // s <= thi + warpLocal <= nblk+6
    bool rowact = (32 * g + 1) <= la;
    int thi = min(nblk - 1, (32 * g + 30 + lb) >> 5);
    int thi7 = min(nblk - 1, (254 + lb) >> 5);    // producer warp 7's last window

    bool consW0 = (half == 1 && warp == 0);
    bool useBig = (g == 0);
    const float* bndSrc = bnd[(warp + 7) & 7];    // warp 0 -> row 7, else warp-1
    bool wrS = (lane == 31 && warp < 7);
    bool wrG = (half == 0 && warp == 7 && lane == 31);
    float* gb = g_bnd + pair * RSG;
    int* gc = g_cnt + pair;
    int seen = 0;

    for (int s = 0; s < nph; ++s) {
        int t = s - warp;                         // local schedule == R13 global schedule
        if (rowact && t >= g && t <= thi) {
            int k0 = 2 + t * 32;
            float cs[32];
#pragma unroll
            for (int d = 0; d < 32; ++d)
                cs[d] = Dp[(size_t)min(k0 - 2 + d, NDIAG - 1) * T_ + (i - 1)];

            if (consW0) {                         // cross-CTA wait + stage (once per window)
                int need = 32 * min(t, thi7) + 33;
                while (seen < need)
                    asm volatile("ld.acquire.gpu.b32 %0, [%1];"
                                 : "=r"(seen) : "l"(gc) : "memory");
                float bv = gb[k0 - 1 + lane];     // ordered after acquire
                bnd[7][(k0 - 1 + lane) & 127] = bv;
                __syncwarp();
            }

            bool full = (32 * g + 32 <= la) && (k0 >= 32 * g + 33)
                     && (k0 + 31 <= 32 * g + 1 + lb);
            if (full) {
#pragma unroll
                for (int d = 0; d < 32; ++d) {
                    int k = k0 + d;
                    float n1 = __shfl_up_sync(0xffffffffu, p1, 1);
                    if (lane == 0)
                        n1 = useBig ? BIGV : bndSrc[(k - 1) & 127];
                    float pmn = fminf(n1, n1p);
                    float pmx = fmaxf(n1, n1p);
                    float psm = n1 + n1p;
                    n1p = n1;
                    float m = fminf(pmn, p1);
                    float M = fmaxf(pmx, p1);
                    float mid = (psm + p1) - m - M;
                    float S2 = 1.f + fex2((m - mid) * c1) + fex2((m - M) * c1);
                    float r = cs[d] + m - gln2 * flg2(S2);
                    p1 = r;
                    if (wrS) bnd[warp][k & 127] = r;
                    if (wrG) gb[k] = r;
                }
            } else {
                bool iact = (i <= la);
#pragma unroll
                for (int d = 0; d < 32; ++d) {
                    int k = k0 + d;
                    float n1 = __shfl_up_sync(0xffffffffu, p1, 1);
                    if (lane == 0)
                        n1 = useBig ? BIGV : bndSrc[(k - 1) & 127];
                    float pmn = fminf(n1, n1p);
                    float pmx = fmaxf(n1, n1p);
                    float psm = n1 + n1p;
                    n1p = n1;
                    float m = fminf(pmn, p1);
                    float M = fmaxf(pmx, p1);
                    float mid = (psm + p1) - m - M;
                    float S2 = 1.f + fex2((m - mid) * c1) + fex2((m - M) * c1);
                    float r = cs[d] + m - gln2 * flg2(S2);
                    bool act = iact && (k > i) && (k <= i + lb);
                    r = act ? r : BIGV;
                    p1 = r;
                    if (wrS) bnd[warp][k & 127] = r;
                    if (wrG) gb[k] = r;
                    if (k == kmax && i == la) g_raw[pair] = r;
                }
            }
            if (wrG)                              // publish window completion
                asm volatile("st.release.gpu.b32 [%0], %1;"
                             :: "l"(gc), "r"(32 * t + 33) : "memory");
        }
        __syncthreads();
    }
}

// ---------------------------------------------------------------------------
// Kernel C: finishing — parallel reductions (deterministic fixed-order trees)
// ---------------------------------------------------------------------------
__device__ __forceinline__ float warp_sum(float v) {
#pragma unroll
    for (int o = 16; o; o >>= 1) v += __shfl_down_sync(0xffffffffu, v, o);
    return v;
}

__device__ float block_sum(float v, float* part, int tid) {
    float s = warp_sum(v);
    __syncthreads();
    if ((tid & 31) == 0) part[tid >> 5] = s;
    __syncthreads();
    if (tid < 32) {
        float x = (tid < 16) ? part[tid] : 0.f;
        x = warp_sum(x);
        if (tid == 0) part[0] = x;
    }
    __syncthreads();
    return part[0];
}

__global__ __launch_bounds__(512) void final_kernel(const int* __restrict__ lens,
                                                    float* __restrict__ out) {
    __shared__ float sG[44 * 44];
    __shared__ float part[32];
    __shared__ float dist[60];
    __shared__ float sTotal;
    int tid = threadIdx.x;

    for (int t = tid; t < 44 * 44; t += 512) {
        int a = t / 44, b = t % 44;
        float s = 0.f;
#pragma unroll 8
        for (int blk = 0; blk < 64; ++blk) s += g_Gp[blk * 2304 + a * 48 + b];
        sG[t] = s;
    }
    if (tid < 60) {
        int w = tid / 15, jj = tid % 15 + 1;
        dist[tid] = g_raw[tid] / (float)(lens[w * 16] + lens[w * 16 + jj]);
    }
    __syncthreads();

    if (tid == 0) {
        float total = 0.f;
        for (int w = 0; w < 4; ++w) {
            const float* dw = dist + w * 15;
            float mg = 0.f;
            for (int g = 0; g < 5; ++g) mg += dw[g];
            mg *= 0.2f;
            float dk = sqrtf(fabsf(mg));
            float dg[5], dn[10];
            for (int g = 0; g < 5; ++g) dg[g] = dw[g] / dk;
            for (int s = 0; s < 10; ++s) dn[s] = dw[5 + s] / dk;
            float sum = 0.f; int cnt = 0;
            for (int g = 0; g < 5; ++g)
                for (int s = 0; s < 10; ++s) {
                    float v = dg[g] + 1.0f - dn[s];
                    if (v > 0.f) { sum += v; cnt++; }
                }
            float ca = 0.f, cb = 0.f;
            for (int g = 0; g < 5; ++g) ca += dg[g];
            ca *= 0.2f;
            for (int s = 0; s < 5; ++s) cb += dn[s];
            cb *= 0.2f;
            float intra = 0.f;
            for (int g = 0; g < 5; ++g) intra += dg[g] - ca;
            float inter = fmaxf(0.f, 1.0f - fabsf(ca - cb));
            float lv = sum / ((float)cnt + 1.f);
            total += lv + intra * 0.1f + inter * 0.1f;
        }
        sTotal = total * 0.25f;
    }
    __syncthreads();

    const int pwi[9] = {0, 0, 0, 1, 1, 2, 2, 3, 3};
    const int pwj[9] = {1, 2, 3, 2, 3, 1, 3, 1, 2};
    int a = tid / 22, b = tid % 22;
    float mmax = 0.f;
#pragma unroll 1
    for (int pp = 0; pp < 9; ++pp) {
        float l2 = 0.f;
        if (tid < 484) {
            int ra = (a < 11) ? pwi[pp] * 11 + a : pwj[pp] * 11 + (a - 11);
            int rb = (b < 11) ? pwi[pp] * 11 + b : pwj[pp] * 11 + (b - 11);
            l2 = sG[ra * 44 + ra] + sG[rb * 44 + rb] - 2.f * sG[ra * 44 + rb];
        }
        float bw = block_sum(l2, part, tid) * (0.25f / 462.f);
        float kk = 0.f;
        if (tid < 484) {
            float r0 = -l2 / bw * 1.4426950408889634f;   // log2(e)
            kk = fex2(r0) + fex2(r0 * 0.5f) + fex2(r0 * 0.25f)
               + fex2(r0 * 0.125f) + fex2(r0 * 0.0625f);
        }
        float sgn = ((a < 11) == (b < 11)) ? kk : -kk;
        float msum = block_sum(tid < 484 ? sgn : 0.f, part, tid);
        mmax = fmaxf(mmax, msum * (1.f / 121.f));
    }
    if (tid == 0) out[0] = sTotal + mmax * 0.1f;
}

// ---------------------------------------------------------------------------
extern "C" void kernel_launch(void* const* d_in, const int* in_sizes, int n_in,
                              void* d_out, int out_size) {
    const float* data = (const float*)d_in[0];
    const int* lens = (const int*)d_in[1];
    float* out = (float*)d_out;

    dim3 gA(8, 8, NPAIR);
    cost_kernel<<<gA, 256>>>(data, lens);
    dtw_gram_kernel<<<2 * NPAIR + 64, 256>>>(data, lens);
    final_kernel<<<1, 512>>>(lens, out);
}